// round 12
// baseline (speedup 1.0000x reference)
#include <cuda_runtime.h>
#include <cuda_bf16.h>
#include <cstdint>
#include <float.h>

#define W 128
#define BINS 50
#define NBOUND (BINS - 1)
#define THREADS 256
#define NWARP (THREADS / 32)
#define FULL 0xFFFFFFFFu

__global__ __launch_bounds__(THREADS, 8)
void mtf_kernel(const float* __restrict__ X, float* __restrict__ out, int S) {
    __shared__ float bnd[NBOUND];
    __shared__ int   bins[W + 1];          // +1 pad so bins[t+1] reads are in-bounds
    __shared__ float smn[NWARP], smx[NWARP];
    __shared__ float bmn, bmx;

    const int s    = blockIdx.x;
    const int tid  = threadIdx.x;
    const int lane = tid & 31;
    const int wid  = tid >> 5;

    if (s >= S) return;

    const float* x = X + (size_t)s * W;

    // Boundaries: linspace(-1, 1, 51)[1:-1].
    if (tid < NBOUND) {
        bnd[tid] = (float)(-1.0 + (2.0 * (double)(tid + 1)) / 50.0);
    }
    if (tid == 0) bins[W] = 0;   // pad

    // Load series value (threads 0..127) and block min/max.
    float v = 0.0f;
    if (tid < W) v = x[tid];
    float mn = (tid < W) ? v : FLT_MAX;
    float mx = (tid < W) ? v : -FLT_MAX;
    #pragma unroll
    for (int o = 16; o > 0; o >>= 1) {
        mn = fminf(mn, __shfl_xor_sync(FULL, mn, o));
        mx = fmaxf(mx, __shfl_xor_sync(FULL, mx, o));
    }
    if (lane == 0) { smn[wid] = mn; smx[wid] = mx; }
    __syncthreads();
    if (wid == 0) {
        float a = (lane < NWARP) ? smn[lane] : FLT_MAX;
        float b = (lane < NWARP) ? smx[lane] : -FLT_MAX;
        #pragma unroll
        for (int o = 4; o > 0; o >>= 1) {
            a = fminf(a, __shfl_xor_sync(FULL, a, o));
            b = fmaxf(b, __shfl_xor_sync(FULL, b, o));
        }
        if (lane == 0) { bmn = a; bmx = b; }
    }
    __syncthreads();

    // Scale into [-1,1] (same op order as reference) and bucketize.
    if (tid < W) {
        float denom = bmx - bmn + 1e-6f;
        float t = (v - bmn) / denom;
        float xsc = t * 2.0f + (-1.0f);
        int cnt = 0;
        #pragma unroll
        for (int k = 0; k < NBOUND; k++) cnt += (bnd[k] < xsc) ? 1 : 0;
        bins[tid] = cnt;
    }
    __syncthreads();

    // Lane's 4 column bins (t2 = lane, lane+32, lane+64, lane+96)
    // and the corresponding NEXT bins (bins[t2+1]) for transition counting.
    const int c0 = bins[lane];
    const int c1 = bins[lane + 32];
    const int c2 = bins[lane + 64];
    const int c3 = bins[lane + 96];
    const int n0 = bins[lane + 1];
    const int n1 = bins[lane + 33];
    const int n2 = bins[lane + 65];
    const int n3 = bins[lane + 97];   // lane 31 -> bins[128] = pad (t=127 never a source)

    // Per bin-row b1: ballot masks give destination rows, source set, row sum,
    // and (via shfl of next-bins over source bits) the transition counts.
    float* o = out + (size_t)s * W * W;
    for (int b1 = wid; b1 < BINS; b1 += NWARP) {
        unsigned m0 = __ballot_sync(FULL, c0 == b1);
        unsigned m1 = __ballot_sync(FULL, c1 == b1);
        unsigned m2 = __ballot_sync(FULL, c2 == b1);
        unsigned m3 = __ballot_sync(FULL, c3 == b1);
        if ((m0 | m1 | m2 | m3) == 0u) continue;   // row never referenced

        unsigned s3 = m3 & 0x7FFFFFFFu;            // exclude t=127 as source
        int rowsum = __popc(m0) + __popc(m1) + __popc(m2) + __popc(s3);
        float rinv = (rowsum == 0) ? 1.0f : (1.0f / (float)rowsum);

        // mtm[b1][c_j] = #{source t : bins[t+1] == c_j}
        int cnt0 = 0, cnt1 = 0, cnt2 = 0, cnt3 = 0;
        unsigned t;
        t = m0; while (t) { int j = __ffs(t) - 1; t &= t - 1;
            int nb = __shfl_sync(FULL, n0, j);
            cnt0 += (nb == c0); cnt1 += (nb == c1); cnt2 += (nb == c2); cnt3 += (nb == c3); }
        t = m1; while (t) { int j = __ffs(t) - 1; t &= t - 1;
            int nb = __shfl_sync(FULL, n1, j);
            cnt0 += (nb == c0); cnt1 += (nb == c1); cnt2 += (nb == c2); cnt3 += (nb == c3); }
        t = m2; while (t) { int j = __ffs(t) - 1; t &= t - 1;
            int nb = __shfl_sync(FULL, n2, j);
            cnt0 += (nb == c0); cnt1 += (nb == c1); cnt2 += (nb == c2); cnt3 += (nb == c3); }
        t = s3; while (t) { int j = __ffs(t) - 1; t &= t - 1;
            int nb = __shfl_sync(FULL, n3, j);
            cnt0 += (nb == c0); cnt1 += (nb == c1); cnt2 += (nb == c2); cnt3 += (nb == c3); }

        float v0 = (float)cnt0 * rinv;
        float v1 = (float)cnt1 * rinv;
        float v2 = (float)cnt2 * rinv;
        float v3 = (float)cnt3 * rinv;

        // Store the row to every destination t1 with bins[t1] == b1.
        while (m0) {
            int t1 = __ffs(m0) - 1; m0 &= m0 - 1;
            float* d = o + t1 * W + lane;
            d[0] = v0; d[32] = v1; d[64] = v2; d[96] = v3;
        }
        while (m1) {
            int t1 = 32 + __ffs(m1) - 1; m1 &= m1 - 1;
            float* d = o + t1 * W + lane;
            d[0] = v0; d[32] = v1; d[64] = v2; d[96] = v3;
        }
        while (m2) {
            int t1 = 64 + __ffs(m2) - 1; m2 &= m2 - 1;
            float* d = o + t1 * W + lane;
            d[0] = v0; d[32] = v1; d[64] = v2; d[96] = v3;
        }
        while (m3) {
            int t1 = 96 + __ffs(m3) - 1; m3 &= m3 - 1;
            float* d = o + t1 * W + lane;
            d[0] = v0; d[32] = v1; d[64] = v2; d[96] = v3;
        }
    }
}

extern "C" void kernel_launch(void* const* d_in, const int* in_sizes, int n_in,
                              void* d_out, int out_size) {
    const float* X = (const float*)d_in[0];
    float* out = (float*)d_out;
    int S = in_sizes[0] / W;   // 256*6 = 1536 series
    mtf_kernel<<<S, THREADS>>>(X, out, S);
}

// round 13
// speedup vs baseline: 1.0784x; 1.0784x over previous
#include <cuda_runtime.h>
#include <cuda_bf16.h>
#include <cstdint>
#include <float.h>

#define W 128
#define BINS 50
#define NBOUND (BINS - 1)
#define MPAD 64
#define THREADS 256
#define NWARP (THREADS / 32)
#define FULL 0xFFFFFFFFu

__global__ __launch_bounds__(THREADS, 8)
void mtf_kernel(const float* __restrict__ X, float* __restrict__ out, int S) {
    __shared__ float bnd[NBOUND];
    __shared__ __align__(16) int bins[W];
    __shared__ float mtm[BINS * MPAD];
    __shared__ float smn[NWARP], smx[NWARP];
    __shared__ float bmn, bmx;

    const int s    = blockIdx.x;
    const int tid  = threadIdx.x;
    const int lane = tid & 31;
    const int wid  = tid >> 5;

    if (s >= S) return;

    const float* x = X + (size_t)s * W;

    // Boundaries: linspace(-1, 1, 51)[1:-1].
    if (tid < NBOUND) {
        bnd[tid] = (float)(-1.0 + (2.0 * (double)(tid + 1)) / 50.0);
    }
    // Zero transition counts.
    for (int i = tid; i < BINS * MPAD; i += THREADS) mtm[i] = 0.0f;

    // Load series value (threads 0..127) and block min/max.
    float v = 0.0f;
    if (tid < W) v = x[tid];
    float mn = (tid < W) ? v : FLT_MAX;
    float mx = (tid < W) ? v : -FLT_MAX;
    #pragma unroll
    for (int o = 16; o > 0; o >>= 1) {
        mn = fminf(mn, __shfl_xor_sync(FULL, mn, o));
        mx = fmaxf(mx, __shfl_xor_sync(FULL, mx, o));
    }
    if (lane == 0) { smn[wid] = mn; smx[wid] = mx; }
    __syncthreads();
    if (wid == 0) {
        float a = (lane < NWARP) ? smn[lane] : FLT_MAX;
        float b = (lane < NWARP) ? smx[lane] : -FLT_MAX;
        #pragma unroll
        for (int o = 4; o > 0; o >>= 1) {
            a = fminf(a, __shfl_xor_sync(FULL, a, o));
            b = fmaxf(b, __shfl_xor_sync(FULL, b, o));
        }
        if (lane == 0) { bmn = a; bmx = b; }
    }
    __syncthreads();

    // Scale into [-1,1] (same op order as reference) and bucketize.
    if (tid < W) {
        float denom = bmx - bmn + 1e-6f;
        float t = (v - bmn) / denom;
        float xsc = t * 2.0f + (-1.0f);
        int cnt = 0;
        #pragma unroll
        for (int k = 0; k < NBOUND; k++) cnt += (bnd[k] < xsc) ? 1 : 0;
        bins[tid] = cnt;
    }
    __syncthreads();

    // Transition histogram (padded rows).
    if (tid < W - 1) {
        atomicAdd(&mtm[bins[tid] * MPAD + bins[tid + 1]], 1.0f);
    }
    // Contiguous layout: lane owns columns t2 = 4*lane .. 4*lane+3 (one LDS.128).
    const int4 c = reinterpret_cast<const int4*>(bins)[lane];
    __syncthreads();

    // Per bin-row b1: ballots give destination rows AND the row sum
    // (rowsum(b1) = #{t in 0..126 : bins[t]==b1}; t=127 never a source).
    // Lane 31's c.w covers t=127: mask that single bit out of the count.
    float* o = out + (size_t)s * W * W;
    for (int b1 = wid; b1 < BINS; b1 += NWARP) {
        unsigned m0 = __ballot_sync(FULL, c.x == b1);
        unsigned m1 = __ballot_sync(FULL, c.y == b1);
        unsigned m2 = __ballot_sync(FULL, c.z == b1);
        unsigned m3 = __ballot_sync(FULL, c.w == b1);
        if ((m0 | m1 | m2 | m3) == 0u) continue;

        int rowsum = __popc(m0) + __popc(m1) + __popc(m2) + __popc(m3 & 0x7FFFFFFFu);
        float rinv = (rowsum == 0) ? 1.0f : (1.0f / (float)rowsum);

        const float* row = &mtm[b1 * MPAD];
        float4 val;
        val.x = row[c.x] * rinv;
        val.y = row[c.y] * rinv;
        val.z = row[c.z] * rinv;
        val.w = row[c.w] * rinv;

        // Destinations t1 = 4*idx + j; one streaming STG.128 per row per lane.
        while (m0) {
            int t1 = 4 * (__ffs(m0) - 1); m0 &= m0 - 1;
            __stcs(reinterpret_cast<float4*>(o + t1 * W) + lane, val);
        }
        while (m1) {
            int t1 = 4 * (__ffs(m1) - 1) + 1; m1 &= m1 - 1;
            __stcs(reinterpret_cast<float4*>(o + t1 * W) + lane, val);
        }
        while (m2) {
            int t1 = 4 * (__ffs(m2) - 1) + 2; m2 &= m2 - 1;
            __stcs(reinterpret_cast<float4*>(o + t1 * W) + lane, val);
        }
        while (m3) {
            int t1 = 4 * (__ffs(m3) - 1) + 3; m3 &= m3 - 1;
            __stcs(reinterpret_cast<float4*>(o + t1 * W) + lane, val);
        }
    }
}

extern "C" void kernel_launch(void* const* d_in, const int* in_sizes, int n_in,
                              void* d_out, int out_size) {
    const float* X = (const float*)d_in[0];
    float* out = (float*)d_out;
    int S = in_sizes[0] / W;   // 256*6 = 1536 series
    mtf_kernel<<<S, THREADS>>>(X, out, S);
}

// round 14
// speedup vs baseline: 1.1738x; 1.0884x over previous
#include <cuda_runtime.h>
#include <cuda_bf16.h>
#include <cstdint>
#include <float.h>

#define W 128
#define BINS 50
#define NBOUND (BINS - 1)
#define MPAD 64
#define THREADS 256
#define NWARP (THREADS / 32)
#define FULL 0xFFFFFFFFu

__global__ __launch_bounds__(THREADS, 8)
void mtf_kernel(const float* __restrict__ X, float* __restrict__ out, int S) {
    __shared__ __align__(16) int bins[W];
    __shared__ float mtm[BINS * MPAD];
    __shared__ float smn[NWARP], smx[NWARP];
    __shared__ float bmn, bmx;

    const int s    = blockIdx.x;
    const int tid  = threadIdx.x;
    const int lane = tid & 31;
    const int wid  = tid >> 5;

    if (s >= S) return;

    const float* x = X + (size_t)s * W;

    // Zero transition counts.
    for (int i = tid; i < BINS * MPAD; i += THREADS) mtm[i] = 0.0f;

    // Load series value (threads 0..127) and block min/max.
    float v = 0.0f;
    if (tid < W) v = x[tid];
    float mn = (tid < W) ? v : FLT_MAX;
    float mx = (tid < W) ? v : -FLT_MAX;
    #pragma unroll
    for (int o = 16; o > 0; o >>= 1) {
        mn = fminf(mn, __shfl_xor_sync(FULL, mn, o));
        mx = fmaxf(mx, __shfl_xor_sync(FULL, mx, o));
    }
    if (lane == 0) { smn[wid] = mn; smx[wid] = mx; }
    __syncthreads();
    if (wid == 0) {
        float a = (lane < NWARP) ? smn[lane] : FLT_MAX;
        float b = (lane < NWARP) ? smx[lane] : -FLT_MAX;
        #pragma unroll
        for (int o = 4; o > 0; o >>= 1) {
            a = fminf(a, __shfl_xor_sync(FULL, a, o));
            b = fmaxf(b, __shfl_xor_sync(FULL, b, o));
        }
        if (lane == 0) { bmn = a; bmx = b; }
    }
    __syncthreads();

    // Scale into [-1,1] (same op order as reference) and bucketize against
    // COMPILE-TIME-CONSTANT boundaries: linspace(-1,1,51)[1:-1].
    // Fully unrolled -> each boundary is an FP32 immediate (FSETP-imm, no LDS).
    if (tid < W) {
        float denom = bmx - bmn + 1e-6f;
        float t = (v - bmn) / denom;
        float xsc = t * 2.0f + (-1.0f);
        int cnt = 0;
        #pragma unroll
        for (int k = 1; k < BINS; k++) {
            float b = (float)(-1.0 + (2.0 * (double)k) / 50.0);  // constant-folded
            cnt += (b < xsc) ? 1 : 0;
        }
        bins[tid] = cnt;
    }
    __syncthreads();

    // Transition histogram (padded rows).
    if (tid < W - 1) {
        atomicAdd(&mtm[bins[tid] * MPAD + bins[tid + 1]], 1.0f);
    }
    // Contiguous layout: lane owns columns t2 = 4*lane .. 4*lane+3 (one LDS.128).
    const int4 c = reinterpret_cast<const int4*>(bins)[lane];
    __syncthreads();

    // Per bin-row b1: ballots give destination rows AND the row sum
    // (rowsum(b1) = #{t in 0..126 : bins[t]==b1}; t=127 never a source).
    float* o = out + (size_t)s * W * W;
    for (int b1 = wid; b1 < BINS; b1 += NWARP) {
        unsigned m0 = __ballot_sync(FULL, c.x == b1);
        unsigned m1 = __ballot_sync(FULL, c.y == b1);
        unsigned m2 = __ballot_sync(FULL, c.z == b1);
        unsigned m3 = __ballot_sync(FULL, c.w == b1);
        if ((m0 | m1 | m2 | m3) == 0u) continue;

        int rowsum = __popc(m0) + __popc(m1) + __popc(m2) + __popc(m3 & 0x7FFFFFFFu);
        float rinv = (rowsum == 0) ? 1.0f : (1.0f / (float)rowsum);

        const float* row = &mtm[b1 * MPAD];
        float4 val;
        val.x = row[c.x] * rinv;
        val.y = row[c.y] * rinv;
        val.z = row[c.z] * rinv;
        val.w = row[c.w] * rinv;

        // Destinations t1 = 4*idx + j; one streaming STG.128 per row per lane.
        while (m0) {
            int t1 = 4 * (__ffs(m0) - 1); m0 &= m0 - 1;
            __stcs(reinterpret_cast<float4*>(o + t1 * W) + lane, val);
        }
        while (m1) {
            int t1 = 4 * (__ffs(m1) - 1) + 1; m1 &= m1 - 1;
            __stcs(reinterpret_cast<float4*>(o + t1 * W) + lane, val);
        }
        while (m2) {
            int t1 = 4 * (__ffs(m2) - 1) + 2; m2 &= m2 - 1;
            __stcs(reinterpret_cast<float4*>(o + t1 * W) + lane, val);
        }
        while (m3) {
            int t1 = 4 * (__ffs(m3) - 1) + 3; m3 &= m3 - 1;
            __stcs(reinterpret_cast<float4*>(o + t1 * W) + lane, val);
        }
    }
}

extern "C" void kernel_launch(void* const* d_in, const int* in_sizes, int n_in,
                              void* d_out, int out_size) {
    const float* X = (const float*)d_in[0];
    float* out = (float*)d_out;
    int S = in_sizes[0] / W;   // 256*6 = 1536 series
    mtf_kernel<<<S, THREADS>>>(X, out, S);
}